// round 1
// baseline (speedup 1.0000x reference)
#include <cuda_runtime.h>
#include <math.h>
#include <stdint.h>

#define B_ 16
#define T_ 256
#define E_ 512
#define H_ 1024
#define V_ 32000
#define G4 4096                         // 4*H
#define LOGITS_ELEMS (B_*T_*V_)         // 131072000

typedef unsigned long long ull;

// ---- scratch (static device allocations are permitted) ----
__device__ float g_xproj[(size_t)T_*B_*G4];   // 64 MB : x-projection for current layer
__device__ float g_ys[(size_t)T_*B_*H_];      // 16 MB : layer outputs (time-major [T,B,H])
__device__ float g_h[2*B_*H_];                // double-buffered hidden state
__device__ float g_c[B_*H_];                  // cell state

// ---- packed fp32x2 helpers (Blackwell dual fp32 pipe) ----
__device__ __forceinline__ ull pk2(float x, float y){
    ull r; asm("mov.b64 %0,{%1,%2};" : "=l"(r) : "f"(x), "f"(y)); return r;
}
__device__ __forceinline__ float2 upk2(ull u){
    float2 f; asm("mov.b64 {%0,%1},%2;" : "=f"(f.x), "=f"(f.y) : "l"(u)); return f;
}
__device__ __forceinline__ ull ffma2(ull a, ull b, ull c){
    ull d; asm("fma.rn.f32x2 %0,%1,%2,%3;" : "=l"(d) : "l"(a), "l"(b), "l"(c)); return d;
}
__device__ __forceinline__ float sigmoidf_(float x){ return 1.f/(1.f + expf(-x)); }

// ============================================================================
// SGEMM (NT): C[m,n] = sum_k A[m,k]*B[n,k] + bias1[n] (+bias2[n])
// GATHER: A row m comes from emb[x[b*T+t]] with m = t*B + b
// REMAP : output row m -> (m%B)*T + m/B   (time-major -> [B,T] order for logits)
// Tile 128x128xBK16, 256 threads, 8x8 per thread, fp32x2-packed along M.
// All problem dims are multiples of the tile sizes; no bounds checks needed.
// ============================================================================
template<int GATHER, int REMAP>
__global__ __launch_bounds__(256)
void sgemm_nt(int M, int N, int K,
              const float* __restrict__ A, int lda,
              const int* __restrict__ gidx,
              const float* __restrict__ Bm, int ldb,
              const float* __restrict__ bias1, const float* __restrict__ bias2,
              float* __restrict__ C, int ldc)
{
    __shared__ float As[16][128];
    __shared__ float Bs[16][128];
    const int tid = threadIdx.x;
    const int tx = tid & 15, ty = tid >> 4;
    const int m0 = blockIdx.y * 128, n0 = blockIdx.x * 128;

    // global-load mapping: thread covers rows r0 and r0+64, 4 consecutive k at kq
    const int r0 = tid >> 2;          // 0..63
    const int kq = (tid & 3) * 4;     // 0,4,8,12

    const float *aptr0, *aptr1;
    if (GATHER) {
        int m = m0 + r0;      int bb = m & 15, tt = m >> 4;
        aptr0 = A + (size_t)gidx[bb*T_ + tt] * lda + kq;
        m = m0 + r0 + 64;     bb = m & 15; tt = m >> 4;
        aptr1 = A + (size_t)gidx[bb*T_ + tt] * lda + kq;
    } else {
        aptr0 = A + (size_t)(m0 + r0) * lda + kq;
        aptr1 = A + (size_t)(m0 + r0 + 64) * lda + kq;
    }
    const float* bptr0 = Bm + (size_t)(n0 + r0) * ldb + kq;
    const float* bptr1 = Bm + (size_t)(n0 + r0 + 64) * ldb + kq;

    ull acc[4][8];
    #pragma unroll
    for (int i = 0; i < 4; i++)
        #pragma unroll
        for (int j = 0; j < 8; j++) acc[i][j] = 0ull;   // (0.f,0.f)

    for (int kt = 0; kt < K; kt += 16) {
        float4 a0 = *(const float4*)(aptr0 + kt);
        float4 a1 = *(const float4*)(aptr1 + kt);
        float4 b0 = *(const float4*)(bptr0 + kt);
        float4 b1 = *(const float4*)(bptr1 + kt);
        As[kq+0][r0]    = a0.x; As[kq+1][r0]    = a0.y; As[kq+2][r0]    = a0.z; As[kq+3][r0]    = a0.w;
        As[kq+0][r0+64] = a1.x; As[kq+1][r0+64] = a1.y; As[kq+2][r0+64] = a1.z; As[kq+3][r0+64] = a1.w;
        Bs[kq+0][r0]    = b0.x; Bs[kq+1][r0]    = b0.y; Bs[kq+2][r0]    = b0.z; Bs[kq+3][r0]    = b0.w;
        Bs[kq+0][r0+64] = b1.x; Bs[kq+1][r0+64] = b1.y; Bs[kq+2][r0+64] = b1.z; Bs[kq+3][r0+64] = b1.w;
        __syncthreads();
        #pragma unroll
        for (int k = 0; k < 16; k++) {
            const ulonglong2* ap = (const ulonglong2*)&As[k][ty*8];
            ulonglong2 av0 = ap[0], av1 = ap[1];
            ull a2[4] = {av0.x, av0.y, av1.x, av1.y};   // m-pairs (0,1)(2,3)(4,5)(6,7)
            float4 bv0 = *(const float4*)&Bs[k][tx*8];
            float4 bv1 = *(const float4*)(&Bs[k][tx*8] + 4);
            ull bp[8] = {pk2(bv0.x,bv0.x), pk2(bv0.y,bv0.y), pk2(bv0.z,bv0.z), pk2(bv0.w,bv0.w),
                         pk2(bv1.x,bv1.x), pk2(bv1.y,bv1.y), pk2(bv1.z,bv1.z), pk2(bv1.w,bv1.w)};
            #pragma unroll
            for (int i = 0; i < 4; i++)
                #pragma unroll
                for (int j = 0; j < 8; j++)
                    acc[i][j] = ffma2(a2[i], bp[j], acc[i][j]);
        }
        __syncthreads();
    }

    // epilogue
    float bb1[8];
    {
        float4 u = *(const float4*)&bias1[n0 + tx*8];
        float4 v = *(const float4*)(&bias1[n0 + tx*8] + 4);
        bb1[0]=u.x; bb1[1]=u.y; bb1[2]=u.z; bb1[3]=u.w;
        bb1[4]=v.x; bb1[5]=v.y; bb1[6]=v.z; bb1[7]=v.w;
        if (bias2) {
            float4 p = *(const float4*)&bias2[n0 + tx*8];
            float4 q = *(const float4*)(&bias2[n0 + tx*8] + 4);
            bb1[0]+=p.x; bb1[1]+=p.y; bb1[2]+=p.z; bb1[3]+=p.w;
            bb1[4]+=q.x; bb1[5]+=q.y; bb1[6]+=q.z; bb1[7]+=q.w;
        }
    }
    #pragma unroll
    for (int r = 0; r < 8; r++) {
        int m = m0 + ty*8 + r;
        int row = REMAP ? ((m & 15)*T_ + (m >> 4)) : m;
        float o[8];
        #pragma unroll
        for (int j = 0; j < 8; j++) {
            float2 v = upk2(acc[r>>1][j]);
            o[j] = ((r & 1) ? v.y : v.x) + bb1[j];
        }
        float4* cp = (float4*)&C[(size_t)row*ldc + n0 + tx*8];
        cp[0] = make_float4(o[0],o[1],o[2],o[3]);
        cp[1] = make_float4(o[4],o[5],o[6],o[7]);
    }
}

// ============================================================================
// Fused LSTM step: gates = xp[t] + h @ Whh^T ; pointwise ; write h,c,ys[t].
// CTA owns gate-interleaved slice {g*H + j : g in 0..3, j in [j0,j0+8)} so the
// pointwise phase needs no cross-CTA data. Threads = 16 k-chunks x 16 batch;
// each thread accumulates 32 n-rows over its 64-k chunk with fp32x2 packed-k
// accumulators; smem reduction over the 16 k-chunks.
// h is double-buffered (hin/hout) to avoid cross-CTA RAW races.
// ============================================================================
__global__ __launch_bounds__(256)
void lstm_step(const float* __restrict__ Whh,   // [4H, H]
               const float* __restrict__ xp,    // [B, 4H] slice at time t
               const float* __restrict__ hin,   // [B, H]
               float* __restrict__ hout,        // [B, H]
               float* __restrict__ cst,         // [B, H]
               float* __restrict__ ys)          // [B, H] slice at time t
{
    __shared__ float red[16][32][16];   // [kchunk][n_local][b]
    __shared__ float gs[32][16];        // reduced gates [n_local][b]
    const int tid = threadIdx.x;
    const int kc = tid >> 4, b = tid & 15;
    const int j0 = blockIdx.x * 8;
    const int k0 = kc * 64;

    ull acc[32];
    #pragma unroll
    for (int a = 0; a < 32; a++) acc[a] = 0ull;

    const float* hb = hin + b*H_ + k0;
    for (int ks = 0; ks < 4; ks++) {            // 4 sub-chunks of 16 k
        const ulonglong2* hp = (const ulonglong2*)(hb + ks*16);
        ulonglong2 h01 = hp[0], h23 = hp[1], h45 = hp[2], h67 = hp[3];
        ull hv[8] = {h01.x,h01.y,h23.x,h23.y,h45.x,h45.y,h67.x,h67.y};
        #pragma unroll
        for (int g = 0; g < 4; g++) {
            #pragma unroll
            for (int jj = 0; jj < 8; jj++) {
                const ulonglong2* wp = (const ulonglong2*)
                    (Whh + (size_t)(g*H_ + j0 + jj)*H_ + k0 + ks*16);
                ulonglong2 w01 = wp[0], w23 = wp[1], w45 = wp[2], w67 = wp[3];
                const int a = g*8 + jj;
                acc[a] = ffma2(w01.x, hv[0], acc[a]);
                acc[a] = ffma2(w01.y, hv[1], acc[a]);
                acc[a] = ffma2(w23.x, hv[2], acc[a]);
                acc[a] = ffma2(w23.y, hv[3], acc[a]);
                acc[a] = ffma2(w45.x, hv[4], acc[a]);
                acc[a] = ffma2(w45.y, hv[5], acc[a]);
                acc[a] = ffma2(w67.x, hv[6], acc[a]);
                acc[a] = ffma2(w67.y, hv[7], acc[a]);
            }
        }
    }
    #pragma unroll
    for (int a = 0; a < 32; a++) {
        float2 v = upk2(acc[a]);
        red[kc][a][b] = v.x + v.y;
    }
    __syncthreads();

    #pragma unroll
    for (int rep = 0; rep < 2; rep++) {
        int o  = tid + rep*256;
        int nl = o >> 4, ob = o & 15;
        float s = 0.f;
        #pragma unroll
        for (int q = 0; q < 16; q++) s += red[q][nl][ob];
        int g = nl >> 3, jj = nl & 7;
        s += xp[(size_t)ob*G4 + g*H_ + j0 + jj];
        gs[nl][ob] = s;
    }
    __syncthreads();

    if (tid < 128) {
        int jj = tid >> 4, ob = tid & 15;
        float iv = sigmoidf_(gs[jj][ob]);          // i
        float fv = sigmoidf_(gs[8  + jj][ob]);     // f
        float gv = tanhf    (gs[16 + jj][ob]);     // g
        float ov = sigmoidf_(gs[24 + jj][ob]);     // o
        int idx = ob*H_ + j0 + jj;
        float cn = fv * cst[idx] + iv * gv;
        float hn = ov * tanhf(cn);
        cst[idx]  = cn;
        hout[idx] = hn;
        ys[idx]   = hn;
    }
}

__global__ void zero_state_kernel() {
    int i = blockIdx.x * 256 + threadIdx.x;
    if (i < 2*B_*H_) g_h[i] = 0.f;
    if (i <   B_*H_) g_c[i] = 0.f;
}

__global__ void copy_state_kernel(const float* __restrict__ h,
                                  const float* __restrict__ c,
                                  float* __restrict__ out, int layer) {
    int i = blockIdx.x * 256 + threadIdx.x;
    if (i < B_*H_) {
        out[(size_t)LOGITS_ELEMS + (size_t)layer*B_*H_ + i]            = h[i];  // h_n
        out[(size_t)LOGITS_ELEMS + (size_t)2*B_*H_ + (size_t)layer*B_*H_ + i] = c[i];  // c_n
    }
}

// ============================================================================
extern "C" void kernel_launch(void* const* d_in, const int* in_sizes, int n_in,
                              void* d_out, int out_size)
{
    const int*   x    = (const int*)  d_in[0];
    const float* emb  = (const float*)d_in[1];
    const float* Wih0 = (const float*)d_in[2];
    const float* Whh0 = (const float*)d_in[3];
    const float* bih0 = (const float*)d_in[4];
    const float* bhh0 = (const float*)d_in[5];
    const float* Wih1 = (const float*)d_in[6];
    const float* Whh1 = (const float*)d_in[7];
    const float* bih1 = (const float*)d_in[8];
    const float* bhh1 = (const float*)d_in[9];
    const float* fcW  = (const float*)d_in[10];
    const float* fcb  = (const float*)d_in[11];
    float* out = (float*)d_out;
    (void)in_sizes; (void)n_in; (void)out_size;

    float *xp, *ys, *hbuf, *cbuf;
    cudaGetSymbolAddress((void**)&xp,   g_xproj);
    cudaGetSymbolAddress((void**)&ys,   g_ys);
    cudaGetSymbolAddress((void**)&hbuf, g_h);
    cudaGetSymbolAddress((void**)&cbuf, g_c);

    // ---- layer 0 ----
    zero_state_kernel<<<128, 256>>>();
    // x_proj0 = gather(emb, x) @ Wih0^T + (bih0 + bhh0)   [T,B,4H]
    sgemm_nt<1,0><<<dim3(G4/128, (B_*T_)/128), 256>>>(
        B_*T_, G4, E_, emb, E_, x, Wih0, E_, bih0, bhh0, xp, G4);
    for (int t = 0; t < T_; t++) {
        lstm_step<<<128, 256>>>(Whh0,
                                xp + (size_t)t*B_*G4,
                                hbuf + (size_t)(t & 1)*B_*H_,
                                hbuf + (size_t)((t & 1) ^ 1)*B_*H_,
                                cbuf,
                                ys + (size_t)t*B_*H_);
    }
    copy_state_kernel<<<64, 256>>>(hbuf, cbuf, out, 0);   // final h in buffer 0 (T even)

    // ---- layer 1 ----
    zero_state_kernel<<<128, 256>>>();
    // x_proj1 = ys0 @ Wih1^T + (bih1 + bhh1)
    sgemm_nt<0,0><<<dim3(G4/128, (B_*T_)/128), 256>>>(
        B_*T_, G4, H_, ys, H_, nullptr, Wih1, H_, bih1, bhh1, xp, G4);
    for (int t = 0; t < T_; t++) {
        lstm_step<<<128, 256>>>(Whh1,
                                xp + (size_t)t*B_*G4,
                                hbuf + (size_t)(t & 1)*B_*H_,
                                hbuf + (size_t)((t & 1) ^ 1)*B_*H_,
                                cbuf,
                                ys + (size_t)t*B_*H_);   // overwrite in place: ys0 no longer needed
    }
    copy_state_kernel<<<64, 256>>>(hbuf, cbuf, out, 1);

    // ---- FC: logits[b,t,:] = ys1[t,b,:] @ fcW^T + fcb (row remap to [B,T]) ----
    sgemm_nt<0,1><<<dim3(V_/128, (B_*T_)/128), 256>>>(
        B_*T_, V_, H_, ys, H_, nullptr, fcW, H_, fcb, nullptr, out, V_);
}

// round 4
// speedup vs baseline: 1.5590x; 1.5590x over previous
#include <cuda_runtime.h>
#include <math.h>
#include <stdint.h>

#define B_ 16
#define T_ 256
#define E_ 512
#define H_ 1024
#define V_ 32000
#define G4 4096                         // 4*H
#define LOGITS_ELEMS (B_*T_*V_)         // 131072000

typedef unsigned long long ull;

// ---- scratch (static device allocations are permitted) ----
__device__ float g_xproj[(size_t)T_*B_*G4];   // 64 MB : x-projection for current layer
__device__ float g_ys[(size_t)T_*B_*H_];      // 16 MB : layer outputs ([T*B][H])
__device__ float g_hT[2][H_*B_];              // double-buffered hidden state, TRANSPOSED [k][b]
__device__ unsigned g_bar;                    // grid barrier counter

// ---- packed fp32x2 helpers (Blackwell dual fp32 pipe) ----
__device__ __forceinline__ ull pk2(float x, float y){
    ull r; asm("mov.b64 %0,{%1,%2};" : "=l"(r) : "f"(x), "f"(y)); return r;
}
__device__ __forceinline__ float2 upk2(ull u){
    float2 f; asm("mov.b64 {%0,%1},%2;" : "=f"(f.x), "=f"(f.y) : "l"(u)); return f;
}
__device__ __forceinline__ ull ffma2(ull a, ull b, ull c){
    ull d; asm("fma.rn.f32x2 %0,%1,%2,%3;" : "=l"(d) : "l"(a), "l"(b), "l"(c)); return d;
}
__device__ __forceinline__ ull add2(ull a, ull b){
    ull d; asm("add.rn.f32x2 %0,%1,%2;" : "=l"(d) : "l"(a), "l"(b)); return d;
}
__device__ __forceinline__ float sig_(float x){ return 1.f/(1.f + __expf(-x)); }
__device__ __forceinline__ float tanh_(float x){ return 2.f/(1.f + __expf(-2.f*x)) - 1.f; }

// ============================================================================
// SGEMM (NT): C[m,n] = sum_k A[m,k]*B[n,k] + bias1[n] (+bias2[n])
// GATHER: A row m comes from emb[x[b*T+t]] with m = t*B + b
// REMAP : output row m -> (m%B)*T + m/B   (time-major -> [B,T] order for logits)
// Tile 128x128xBK16, 256 threads, 8x8 per thread, fp32x2-packed along M.
// ============================================================================
template<int GATHER, int REMAP>
__global__ __launch_bounds__(256)
void sgemm_nt(int M, int N, int K,
              const float* __restrict__ A, int lda,
              const int* __restrict__ gidx,
              const float* __restrict__ Bm, int ldb,
              const float* __restrict__ bias1, const float* __restrict__ bias2,
              float* __restrict__ C, int ldc)
{
    __shared__ float As[16][128];
    __shared__ float Bs[16][128];
    const int tid = threadIdx.x;
    const int tx = tid & 15, ty = tid >> 4;
    const int m0 = blockIdx.y * 128, n0 = blockIdx.x * 128;

    const int r0 = tid >> 2;          // 0..63
    const int kq = (tid & 3) * 4;     // 0,4,8,12

    const float *aptr0, *aptr1;
    if (GATHER) {
        int m = m0 + r0;      int bb = m & 15, tt = m >> 4;
        aptr0 = A + (size_t)gidx[bb*T_ + tt] * lda + kq;
        m = m0 + r0 + 64;     bb = m & 15; tt = m >> 4;
        aptr1 = A + (size_t)gidx[bb*T_ + tt] * lda + kq;
    } else {
        aptr0 = A + (size_t)(m0 + r0) * lda + kq;
        aptr1 = A + (size_t)(m0 + r0 + 64) * lda + kq;
    }
    const float* bptr0 = Bm + (size_t)(n0 + r0) * ldb + kq;
    const float* bptr1 = Bm + (size_t)(n0 + r0 + 64) * ldb + kq;

    ull acc[4][8];
    #pragma unroll
    for (int i = 0; i < 4; i++)
        #pragma unroll
        for (int j = 0; j < 8; j++) acc[i][j] = 0ull;

    for (int kt = 0; kt < K; kt += 16) {
        float4 a0 = *(const float4*)(aptr0 + kt);
        float4 a1 = *(const float4*)(aptr1 + kt);
        float4 b0 = *(const float4*)(bptr0 + kt);
        float4 b1 = *(const float4*)(bptr1 + kt);
        As[kq+0][r0]    = a0.x; As[kq+1][r0]    = a0.y; As[kq+2][r0]    = a0.z; As[kq+3][r0]    = a0.w;
        As[kq+0][r0+64] = a1.x; As[kq+1][r0+64] = a1.y; As[kq+2][r0+64] = a1.z; As[kq+3][r0+64] = a1.w;
        Bs[kq+0][r0]    = b0.x; Bs[kq+1][r0]    = b0.y; Bs[kq+2][r0]    = b0.z; Bs[kq+3][r0]    = b0.w;
        Bs[kq+0][r0+64] = b1.x; Bs[kq+1][r0+64] = b1.y; Bs[kq+2][r0+64] = b1.z; Bs[kq+3][r0+64] = b1.w;
        __syncthreads();
        #pragma unroll
        for (int k = 0; k < 16; k++) {
            const ulonglong2* ap = (const ulonglong2*)&As[k][ty*8];
            ulonglong2 av0 = ap[0], av1 = ap[1];
            ull a2[4] = {av0.x, av0.y, av1.x, av1.y};
            float4 bv0 = *(const float4*)&Bs[k][tx*8];
            float4 bv1 = *(const float4*)(&Bs[k][tx*8] + 4);
            ull bp[8] = {pk2(bv0.x,bv0.x), pk2(bv0.y,bv0.y), pk2(bv0.z,bv0.z), pk2(bv0.w,bv0.w),
                         pk2(bv1.x,bv1.x), pk2(bv1.y,bv1.y), pk2(bv1.z,bv1.z), pk2(bv1.w,bv1.w)};
            #pragma unroll
            for (int i = 0; i < 4; i++)
                #pragma unroll
                for (int j = 0; j < 8; j++)
                    acc[i][j] = ffma2(a2[i], bp[j], acc[i][j]);
        }
        __syncthreads();
    }

    float bb1[8];
    {
        float4 u = *(const float4*)&bias1[n0 + tx*8];
        float4 v = *(const float4*)(&bias1[n0 + tx*8] + 4);
        bb1[0]=u.x; bb1[1]=u.y; bb1[2]=u.z; bb1[3]=u.w;
        bb1[4]=v.x; bb1[5]=v.y; bb1[6]=v.z; bb1[7]=v.w;
        if (bias2) {
            float4 p = *(const float4*)&bias2[n0 + tx*8];
            float4 q = *(const float4*)(&bias2[n0 + tx*8] + 4);
            bb1[0]+=p.x; bb1[1]+=p.y; bb1[2]+=p.z; bb1[3]+=p.w;
            bb1[4]+=q.x; bb1[5]+=q.y; bb1[6]+=q.z; bb1[7]+=q.w;
        }
    }
    #pragma unroll
    for (int r = 0; r < 8; r++) {
        int m = m0 + ty*8 + r;
        int row = REMAP ? ((m & 15)*T_ + (m >> 4)) : m;
        float o[8];
        #pragma unroll
        for (int j = 0; j < 8; j++) {
            float2 v = upk2(acc[r>>1][j]);
            o[j] = ((r & 1) ? v.y : v.x) + bb1[j];
        }
        float4* cp = (float4*)&C[(size_t)row*ldc + n0 + tx*8];
        cp[0] = make_float4(o[0],o[1],o[2],o[3]);
        cp[1] = make_float4(o[4],o[5],o[6],o[7]);
    }
}

// ============================================================================
// Persistent LSTM layer: 128 CTAs (1/SM), each owns gate-interleaved rows
// {g*H + j0+jj : g<4, jj<8} of Whh IN SHARED MEMORY (transposed, 128 KB),
// loops over all T steps with a software grid barrier between steps.
// h state double-buffered in global, TRANSPOSED [k][b]; c lives in registers.
// Inner GEMM: f32x2 packs ROW PAIRS (ull loads from transposed smem),
// h duplicated per-batch; 8-way k-split (warp=k-chunk) + smem reduction.
// Cross-step h coherence: __threadfence() (gpu scope) emits CCTL.IVALL on
// sm_103a, invalidating the SM's L1D before the next step's h reads.
// ============================================================================
#define SMEM_WT_BYTES   131072                     // 1024 x 32 floats
#define SMEM_PT_BYTES   18432                      // 256 cells x 9 ull (pad)
#define SMEM_GS_BYTES   2048                       // 32 x 16 floats
#define SMEM_TOTAL_P    (SMEM_WT_BYTES + SMEM_PT_BYTES + SMEM_GS_BYTES)

__global__ __launch_bounds__(256, 1)
void lstm_layer_persist(const float* __restrict__ Whh,  // [4H][H]
                        const float* __restrict__ xp,   // [T*B][4H]
                        float* __restrict__ ys,         // [T*B][H]
                        float* __restrict__ outHC,      // d_out base (for h_n/c_n)
                        int layer)
{
    extern __shared__ unsigned char smem_raw[];
    float* wT = (float*)smem_raw;                                  // [1024][32]
    ull*   pt = (ull*)(smem_raw + SMEM_WT_BYTES);                  // [256][9]
    float* gs = (float*)(smem_raw + SMEM_WT_BYTES + SMEM_PT_BYTES);// [32][16]

    const int tid = threadIdx.x;
    const int j0  = blockIdx.x * 8;

    // ---- stage Whh slice into smem, transposed [k][n] (once per layer) ----
    #pragma unroll 1
    for (int n = 0; n < 32; n++) {
        int row = (n >> 3) * H_ + j0 + (n & 7);
        float4 v = *(const float4*)&Whh[(size_t)row * H_ + tid * 4];
        wT[(tid*4+0)*32 + n] = v.x;
        wT[(tid*4+1)*32 + n] = v.y;
        wT[(tid*4+2)*32 + n] = v.z;
        wT[(tid*4+3)*32 + n] = v.w;
    }
    __syncthreads();

    // compute-role ids: warp = one k-chunk
    const int kc   = tid >> 5;         // 0..7  : k-chunk (128 k each)
    const int lane = tid & 31;
    const int q    = lane >> 3;        // 0..3  : row-pair group (rows 8q..8q+7)
    const int b0   = (lane & 7) * 2;   // even batch of the pair

    // reducer-role ids: cell = (rowpair rrp, batch rb)
    const int rrp = tid >> 4;          // 0..15
    const int rb  = tid & 15;          // 0..15
    const int rg  = (2*rrp) >> 3;      // gate of rows 2rrp,2rrp+1
    const int rjj = (2*rrp) & 7;       // even -> float2 stays inside one gate
    const size_t xpcol = (size_t)rg*H_ + j0 + rjj;

    float creg = 0.f;                  // cell state for pointwise threads (tid<128)

    for (int t = 0; t < T_; t++) {
        const float* rbuf = g_hT[(t & 1) ^ 1];
        float*       wbuf = g_hT[t & 1];

        // prefetch this cell's xp pair
        float2 xpv = *(const float2*)&xp[(size_t)(t*B_ + rb)*G4 + xpcol];

        float2 gsum;
        if (t > 0) {
            ull acc00=0,acc01=0,acc10=0,acc11=0,acc20=0,acc21=0,acc30=0,acc31=0;
            const int kbase = kc * 128;
            #pragma unroll 16
            for (int kk = 0; kk < 128; kk++) {
                const int k = kbase + kk;
                float2 hv = *(const float2*)&rbuf[k*B_ + b0];
                ull hd0 = pk2(hv.x, hv.x);
                ull hd1 = pk2(hv.y, hv.y);
                const ulonglong2* wp = (const ulonglong2*)&wT[k*32 + q*8];
                ulonglong2 wa = wp[0], wb = wp[1];
                acc00 = ffma2(wa.x, hd0, acc00);  acc01 = ffma2(wa.x, hd1, acc01);
                acc10 = ffma2(wa.y, hd0, acc10);  acc11 = ffma2(wa.y, hd1, acc11);
                acc20 = ffma2(wb.x, hd0, acc20);  acc21 = ffma2(wb.x, hd1, acc21);
                acc30 = ffma2(wb.y, hd0, acc30);  acc31 = ffma2(wb.y, hd1, acc31);
            }
            // partials: cell = (q*4 + i)*16 + batch
            {
                int cb = (q*4)*16 + b0;
                pt[(cb +  0)*9 + kc] = acc00;  pt[(cb +  1)*9 + kc] = acc01;
                pt[(cb + 16)*9 + kc] = acc10;  pt[(cb + 17)*9 + kc] = acc11;
                pt[(cb + 32)*9 + kc] = acc20;  pt[(cb + 33)*9 + kc] = acc21;
                pt[(cb + 48)*9 + kc] = acc30;  pt[(cb + 49)*9 + kc] = acc31;
            }
            __syncthreads();
            ull s = pt[tid*9];
            #pragma unroll
            for (int r = 1; r < 8; r++) s = add2(s, pt[tid*9 + r]);
            gsum = upk2(s);
        } else {
            gsum = make_float2(0.f, 0.f);
        }

        gs[(2*rrp  )*16 + rb] = gsum.x + xpv.x;
        gs[(2*rrp+1)*16 + rb] = gsum.y + xpv.y;
        __syncthreads();

        if (tid < 128) {
            const int jj = tid >> 4, b = tid & 15;
            float gi = gs[       jj *16 + b];
            float gf = gs[( 8 + jj)*16 + b];
            float gg = gs[(16 + jj)*16 + b];
            float go = gs[(24 + jj)*16 + b];
            float iv = sig_(gi), fv = sig_(gf), gv = tanh_(gg), ov = sig_(go);
            creg = fv * creg + iv * gv;
            float hn = ov * tanh_(creg);
            wbuf[(j0 + jj)*B_ + b] = hn;
            ys[(size_t)(t*B_ + b)*H_ + j0 + jj] = hn;
            if (t == T_ - 1) {
                outHC[(size_t)LOGITS_ELEMS + (size_t)layer*B_*H_     + (size_t)b*H_ + j0 + jj] = hn;
                outHC[(size_t)LOGITS_ELEMS + (size_t)(2+layer)*B_*H_ + (size_t)b*H_ + j0 + jj] = creg;
            }
        }
        __syncthreads();

        if (t < T_ - 1) {
            if (tid == 0) {
                __threadfence();                  // release h writes (cumulative)
                atomicAdd(&g_bar, 1u);
                const unsigned target = 128u * (unsigned)(t + 1);
                volatile unsigned* vb = &g_bar;
                while (*vb < target) { }
                __threadfence();                  // acquire + L1D invalidate (CCTL.IVALL)
            }
            __syncthreads();
        }
    }
}

__global__ void zero_bar_kernel() { g_bar = 0u; }

// ============================================================================
extern "C" void kernel_launch(void* const* d_in, const int* in_sizes, int n_in,
                              void* d_out, int out_size)
{
    const int*   x    = (const int*)  d_in[0];
    const float* emb  = (const float*)d_in[1];
    const float* Wih0 = (const float*)d_in[2];
    const float* Whh0 = (const float*)d_in[3];
    const float* bih0 = (const float*)d_in[4];
    const float* bhh0 = (const float*)d_in[5];
    const float* Wih1 = (const float*)d_in[6];
    const float* Whh1 = (const float*)d_in[7];
    const float* bih1 = (const float*)d_in[8];
    const float* bhh1 = (const float*)d_in[9];
    const float* fcW  = (const float*)d_in[10];
    const float* fcb  = (const float*)d_in[11];
    float* out = (float*)d_out;
    (void)in_sizes; (void)n_in; (void)out_size;

    float *xp, *ys;
    cudaGetSymbolAddress((void**)&xp, g_xproj);
    cudaGetSymbolAddress((void**)&ys, g_ys);

    cudaFuncSetAttribute(lstm_layer_persist,
                         cudaFuncAttributeMaxDynamicSharedMemorySize, SMEM_TOTAL_P);

    // ---- layer 0 ----
    sgemm_nt<1,0><<<dim3(G4/128, (B_*T_)/128), 256>>>(
        B_*T_, G4, E_, emb, E_, x, Wih0, E_, bih0, bhh0, xp, G4);
    zero_bar_kernel<<<1, 1>>>();
    lstm_layer_persist<<<128, 256, SMEM_TOTAL_P>>>(Whh0, xp, ys, out, 0);

    // ---- layer 1 ----
    sgemm_nt<0,0><<<dim3(G4/128, (B_*T_)/128), 256>>>(
        B_*T_, G4, H_, ys, H_, nullptr, Wih1, H_, bih1, bhh1, xp, G4);
    zero_bar_kernel<<<1, 1>>>();
    lstm_layer_persist<<<128, 256, SMEM_TOTAL_P>>>(Whh1, xp, ys, out, 1);

    // ---- FC: logits[b,t,:] = ys1[t,b,:] @ fcW^T + fcb ----
    sgemm_nt<0,1><<<dim3(V_/128, (B_*T_)/128), 256>>>(
        B_*T_, V_, H_, ys, H_, nullptr, fcW, H_, fcb, nullptr, out, V_);
}

// round 17
// speedup vs baseline: 2.3225x; 1.4897x over previous
#include <cuda_runtime.h>
#include <cuda_bf16.h>
#include <math.h>
#include <stdint.h>

#define B_ 16
#define T_ 256
#define E_ 512
#define H_ 1024
#define V_ 32000
#define G4 4096                         // 4*H
#define LOGITS_ELEMS (B_*T_*V_)         // 131072000

typedef unsigned long long ull;

// ---- scratch (static device allocations are permitted) ----
__device__ float g_xproj[(size_t)T_*B_*G4];   // 64 MB : x-projection for current layer
__device__ float g_ys[(size_t)T_*B_*H_];      // 16 MB : layer outputs ([T*B][H])
__device__ float g_hT[2][H_*B_];              // double-buffered hidden state, TRANSPOSED [k][b]
__device__ unsigned g_bar;                    // grid barrier counter
// split-bf16 K-stacked operands for the FC GEMM (K' = 3H = 3072)
__device__ __nv_bfloat16 g_a2[(size_t)T_*B_*3*H_];   // 25 MB  : [4096][3072] = [ys_hi|ys_hi|ys_lo]
__device__ __nv_bfloat16 g_b2[(size_t)V_*3*H_];      // 197 MB : [32000][3072] = [W_hi|W_lo|W_hi]

// ---- packed fp32x2 helpers (Blackwell dual fp32 pipe) ----
__device__ __forceinline__ ull pk2(float x, float y){
    ull r; asm("mov.b64 %0,{%1,%2};" : "=l"(r) : "f"(x), "f"(y)); return r;
}
__device__ __forceinline__ float2 upk2(ull u){
    float2 f; asm("mov.b64 {%0,%1},%2;" : "=f"(f.x), "=f"(f.y) : "l"(u)); return f;
}
__device__ __forceinline__ ull ffma2(ull a, ull b, ull c){
    ull d; asm("fma.rn.f32x2 %0,%1,%2,%3;" : "=l"(d) : "l"(a), "l"(b), "l"(c)); return d;
}
__device__ __forceinline__ ull add2(ull a, ull b){
    ull d; asm("add.rn.f32x2 %0,%1,%2;" : "=l"(d) : "l"(a), "l"(b)); return d;
}
__device__ __forceinline__ float sig_(float x){ return 1.f/(1.f + __expf(-x)); }
__device__ __forceinline__ float tanh_(float x){ return 2.f/(1.f + __expf(-2.f*x)) - 1.f; }

__device__ __forceinline__ uint32_t smem_u32(const void* p){
    uint32_t a; asm("{ .reg .u64 t; cvta.to.shared.u64 t, %1; cvt.u32.u64 %0, t; }" : "=r"(a) : "l"(p));
    return a;
}

// SW128 swizzle (128 B rows)
#define SWZ(o)          ((o) ^ (((o) >> 3) & 0x70))

// ldmatrix x4 (sm_80+, valid on compute_103)
#define LDSM_X4(r, addr) \
    asm volatile("ldmatrix.sync.aligned.m8n8.x4.shared.b16 {%0,%1,%2,%3}, [%4];" \
        : "=r"((r)[0]), "=r"((r)[1]), "=r"((r)[2]), "=r"((r)[3]) : "r"(addr))

// bf16 mma m16n8k16 with fp32 accum (sm_80+, valid on compute_103)
#define MMA16816(c, a, b0v, b1v) \
    asm volatile("mma.sync.aligned.m16n8k16.row.col.f32.bf16.bf16.f32 " \
        "{%0,%1,%2,%3},{%4,%5,%6,%7},{%8,%9},{%0,%1,%2,%3};" \
        : "+f"((c)[0]), "+f"((c)[1]), "+f"((c)[2]), "+f"((c)[3]) \
        : "r"((a)[0]), "r"((a)[1]), "r"((a)[2]), "r"((a)[3]), "r"(b0v), "r"(b1v))

// ============================================================================
// SGEMM (NT) fp32 — xproj path (round-4 proven)
// ============================================================================
template<int GATHER, int REMAP>
__global__ __launch_bounds__(256)
void sgemm_nt(int M, int N, int K,
              const float* __restrict__ A, int lda,
              const int* __restrict__ gidx,
              const float* __restrict__ Bm, int ldb,
              const float* __restrict__ bias1, const float* __restrict__ bias2,
              float* __restrict__ C, int ldc)
{
    __shared__ float As[16][128];
    __shared__ float Bs[16][128];
    const int tid = threadIdx.x;
    const int tx = tid & 15, ty = tid >> 4;
    const int m0 = blockIdx.y * 128, n0 = blockIdx.x * 128;

    const int r0 = tid >> 2;
    const int kq = (tid & 3) * 4;

    const float *aptr0, *aptr1;
    if (GATHER) {
        int m = m0 + r0;      int bb = m & 15, tt = m >> 4;
        aptr0 = A + (size_t)gidx[bb*T_ + tt] * lda + kq;
        m = m0 + r0 + 64;     bb = m & 15; tt = m >> 4;
        aptr1 = A + (size_t)gidx[bb*T_ + tt] * lda + kq;
    } else {
        aptr0 = A + (size_t)(m0 + r0) * lda + kq;
        aptr1 = A + (size_t)(m0 + r0 + 64) * lda + kq;
    }
    const float* bptr0 = Bm + (size_t)(n0 + r0) * ldb + kq;
    const float* bptr1 = Bm + (size_t)(n0 + r0 + 64) * ldb + kq;

    ull acc[4][8];
    #pragma unroll
    for (int i = 0; i < 4; i++)
        #pragma unroll
        for (int j = 0; j < 8; j++) acc[i][j] = 0ull;

    for (int kt = 0; kt < K; kt += 16) {
        float4 a0 = *(const float4*)(aptr0 + kt);
        float4 a1 = *(const float4*)(aptr1 + kt);
        float4 b0 = *(const float4*)(bptr0 + kt);
        float4 b1 = *(const float4*)(bptr1 + kt);
        As[kq+0][r0]    = a0.x; As[kq+1][r0]    = a0.y; As[kq+2][r0]    = a0.z; As[kq+3][r0]    = a0.w;
        As[kq+0][r0+64] = a1.x; As[kq+1][r0+64] = a1.y; As[kq+2][r0+64] = a1.z; As[kq+3][r0+64] = a1.w;
        Bs[kq+0][r0]    = b0.x; Bs[kq+1][r0]    = b0.y; Bs[kq+2][r0]    = b0.z; Bs[kq+3][r0]    = b0.w;
        Bs[kq+0][r0+64] = b1.x; Bs[kq+1][r0+64] = b1.y; Bs[kq+2][r0+64] = b1.z; Bs[kq+3][r0+64] = b1.w;
        __syncthreads();
        #pragma unroll
        for (int k = 0; k < 16; k++) {
            const ulonglong2* ap = (const ulonglong2*)&As[k][ty*8];
            ulonglong2 av0 = ap[0], av1 = ap[1];
            ull a2[4] = {av0.x, av0.y, av1.x, av1.y};
            float4 bv0 = *(const float4*)&Bs[k][tx*8];
            float4 bv1 = *(const float4*)(&Bs[k][tx*8] + 4);
            ull bp[8] = {pk2(bv0.x,bv0.x), pk2(bv0.y,bv0.y), pk2(bv0.z,bv0.z), pk2(bv0.w,bv0.w),
                         pk2(bv1.x,bv1.x), pk2(bv1.y,bv1.y), pk2(bv1.z,bv1.z), pk2(bv1.w,bv1.w)};
            #pragma unroll
            for (int i = 0; i < 4; i++)
                #pragma unroll
                for (int j = 0; j < 8; j++)
                    acc[i][j] = ffma2(a2[i], bp[j], acc[i][j]);
        }
        __syncthreads();
    }

    float bb1[8];
    {
        float4 u = *(const float4*)&bias1[n0 + tx*8];
        float4 v = *(const float4*)(&bias1[n0 + tx*8] + 4);
        bb1[0]=u.x; bb1[1]=u.y; bb1[2]=u.z; bb1[3]=u.w;
        bb1[4]=v.x; bb1[5]=v.y; bb1[6]=v.z; bb1[7]=v.w;
        if (bias2) {
            float4 p = *(const float4*)&bias2[n0 + tx*8];
            float4 q = *(const float4*)(&bias2[n0 + tx*8] + 4);
            bb1[0]+=p.x; bb1[1]+=p.y; bb1[2]+=p.z; bb1[3]+=p.w;
            bb1[4]+=q.x; bb1[5]+=q.y; bb1[6]+=q.z; bb1[7]+=q.w;
        }
    }
    #pragma unroll
    for (int r = 0; r < 8; r++) {
        int m = m0 + ty*8 + r;
        int row = REMAP ? ((m & 15)*T_ + (m >> 4)) : m;
        float o[8];
        #pragma unroll
        for (int j = 0; j < 8; j++) {
            float2 v = upk2(acc[r>>1][j]);
            o[j] = ((r & 1) ? v.y : v.x) + bb1[j];
        }
        float4* cp = (float4*)&C[(size_t)row*ldc + n0 + tx*8];
        cp[0] = make_float4(o[0],o[1],o[2],o[3]);
        cp[1] = make_float4(o[4],o[5],o[6],o[7]);
    }
}

// ============================================================================
// Persistent LSTM layer (round-4 proven)
// ============================================================================
#define SMEM_WT_BYTES   131072
#define SMEM_PT_BYTES   18432
#define SMEM_GS_BYTES   2048
#define SMEM_TOTAL_P    (SMEM_WT_BYTES + SMEM_PT_BYTES + SMEM_GS_BYTES)

__global__ __launch_bounds__(256, 1)
void lstm_layer_persist(const float* __restrict__ Whh,
                        const float* __restrict__ xp,
                        float* __restrict__ ys,
                        float* __restrict__ outHC,
                        int layer)
{
    extern __shared__ unsigned char smem_raw[];
    float* wT = (float*)smem_raw;
    ull*   pt = (ull*)(smem_raw + SMEM_WT_BYTES);
    float* gs = (float*)(smem_raw + SMEM_WT_BYTES + SMEM_PT_BYTES);

    const int tid = threadIdx.x;
    const int j0  = blockIdx.x * 8;

    #pragma unroll 1
    for (int n = 0; n < 32; n++) {
        int row = (n >> 3) * H_ + j0 + (n & 7);
        float4 v = *(const float4*)&Whh[(size_t)row * H_ + tid * 4];
        wT[(tid*4+0)*32 + n] = v.x;
        wT[(tid*4+1)*32 + n] = v.y;
        wT[(tid*4+2)*32 + n] = v.z;
        wT[(tid*4+3)*32 + n] = v.w;
    }
    __syncthreads();

    const int kc   = tid >> 5;
    const int lane = tid & 31;
    const int q    = lane >> 3;
    const int b0   = (lane & 7) * 2;

    const int rrp = tid >> 4;
    const int rb  = tid & 15;
    const int rg  = (2*rrp) >> 3;
    const int rjj = (2*rrp) & 7;
    const size_t xpcol = (size_t)rg*H_ + j0 + rjj;

    float creg = 0.f;

    for (int t = 0; t < T_; t++) {
        const float* rbuf = g_hT[(t & 1) ^ 1];
        float*       wbuf = g_hT[t & 1];

        float2 xpv = *(const float2*)&xp[(size_t)(t*B_ + rb)*G4 + xpcol];

        float2 gsum;
        if (t > 0) {
            ull acc00=0,acc01=0,acc10=0,acc11=0,acc20=0,acc21=0,acc30=0,acc31=0;
            const int kbase = kc * 128;
            #pragma unroll 16
            for (int kk = 0; kk < 128; kk++) {
                const int k = kbase + kk;
                float2 hv = *(const float2*)&rbuf[k*B_ + b0];
                ull hd0 = pk2(hv.x, hv.x);
                ull hd1 = pk2(hv.y, hv.y);
                const ulonglong2* wp = (const ulonglong2*)&wT[k*32 + q*8];
                ulonglong2 wa = wp[0], wb = wp[1];
                acc00 = ffma2(wa.x, hd0, acc00);  acc01 = ffma2(wa.x, hd1, acc01);
                acc10 = ffma2(wa.y, hd0, acc10);  acc11 = ffma2(wa.y, hd1, acc11);
                acc20 = ffma2(wb.x, hd0, acc20);  acc21 = ffma2(wb.x, hd1, acc21);
                acc30 = ffma2(wb.y, hd0, acc30);  acc31 = ffma2(wb.y, hd1, acc31);
            }
            {
                int cb = (q*4)*16 + b0;
                pt[(cb +  0)*9 + kc] = acc00;  pt[(cb +  1)*9 + kc] = acc01;
                pt[(cb + 16)*9 + kc] = acc10;  pt[(cb + 17)*9 + kc] = acc11;
                pt[(cb + 32)*9 + kc] = acc20;  pt[(cb + 33)*9 + kc] = acc21;
                pt[(cb + 48)*9 + kc] = acc30;  pt[(cb + 49)*9 + kc] = acc31;
            }
            __syncthreads();
            ull s = pt[tid*9];
            #pragma unroll
            for (int r = 1; r < 8; r++) s = add2(s, pt[tid*9 + r]);
            gsum = upk2(s);
        } else {
            gsum = make_float2(0.f, 0.f);
        }

        gs[(2*rrp  )*16 + rb] = gsum.x + xpv.x;
        gs[(2*rrp+1)*16 + rb] = gsum.y + xpv.y;
        __syncthreads();

        if (tid < 128) {
            const int jj = tid >> 4, b = tid & 15;
            float gi = gs[       jj *16 + b];
            float gf = gs[( 8 + jj)*16 + b];
            float gg = gs[(16 + jj)*16 + b];
            float go = gs[(24 + jj)*16 + b];
            float iv = sig_(gi), fv = sig_(gf), gv = tanh_(gg), ov = sig_(go);
            creg = fv * creg + iv * gv;
            float hn = ov * tanh_(creg);
            wbuf[(j0 + jj)*B_ + b] = hn;
            ys[(size_t)(t*B_ + b)*H_ + j0 + jj] = hn;
            if (t == T_ - 1) {
                outHC[(size_t)LOGITS_ELEMS + (size_t)layer*B_*H_     + (size_t)b*H_ + j0 + jj] = hn;
                outHC[(size_t)LOGITS_ELEMS + (size_t)(2+layer)*B_*H_ + (size_t)b*H_ + j0 + jj] = creg;
            }
        }
        __syncthreads();

        if (t < T_ - 1) {
            if (tid == 0) {
                __threadfence();
                atomicAdd(&g_bar, 1u);
                const unsigned target = 128u * (unsigned)(t + 1);
                volatile unsigned* vb = &g_bar;
                while (*vb < target) { }
                __threadfence();
            }
            __syncthreads();
        }
    }
}

__global__ void zero_bar_kernel() { g_bar = 0u; }

// ============================================================================
// split-bf16 conversion kernels
// A' [4096][3072] = [hi | hi | lo] of ys ; B' [32000][3072] = [hi | lo | hi] of fcW
// ============================================================================
__global__ __launch_bounds__(256)
void conv_a_kernel() {
    int i = blockIdx.x * 256 + threadIdx.x;          // over 4096*1024
    int m = i >> 10, k = i & 1023;
    float f = g_ys[i];
    __nv_bfloat16 hi = __float2bfloat16(f);
    __nv_bfloat16 lo = __float2bfloat16(f - __bfloat162float(hi));
    size_t base = (size_t)m * 3072 + k;
    g_a2[base]        = hi;
    g_a2[base + 1024] = hi;
    g_a2[base + 2048] = lo;
}

__global__ __launch_bounds__(256)
void conv_b_kernel(const float* __restrict__ fcW) {
    int i = blockIdx.x * 256 + threadIdx.x;          // over 32000*1024
    int n = i >> 10, k = i & 1023;
    float f = fcW[i];
    __nv_bfloat16 hi = __float2bfloat16(f);
    __nv_bfloat16 lo = __float2bfloat16(f - __bfloat162float(hi));
    size_t base = (size_t)n * 3072 + k;
    g_b2[base]        = hi;
    g_b2[base + 1024] = lo;
    g_b2[base + 2048] = hi;
}

// ============================================================================
// FC GEMM via mma.sync (HMMA, no 'a'-suffix features needed).
// CTA 128(M) x 128(N), K'=3072 in 48 chunks of 64 bf16.
// 8 warps in 2(m) x 4(n); warp tile 64x32; m16n8k16 bf16 -> fp32 accum.
// SW128-swizzled smem, conflict-free ldmatrix.
// ============================================================================
#define FC_ROWB 6144                       // bytes per K'-row (3072 * 2)
#define FC_CHUNKS 48

__global__ __launch_bounds__(256)
void fc_mma_kernel(const float* __restrict__ fcb, float* __restrict__ out)
{
    __shared__ __align__(128) unsigned char smA[128*128];   // 128 rows x 128 B
    __shared__ __align__(128) unsigned char smB[128*128];

    const int tid  = threadIdx.x;
    const int lane = tid & 31;
    const int w    = tid >> 5;
    const int wm   = w & 1;          // m half (64 rows)
    const int wn   = w >> 1;         // n quarter (32 cols)
    const int m0   = blockIdx.x * 128;   // m fastest -> B' strip L2 reuse
    const int n0   = blockIdx.y * 128;

    const uint32_t sa = smem_u32(smA);
    const uint32_t sb = smem_u32(smB);

    const char* gA = (const char*)g_a2 + (size_t)m0 * FC_ROWB;
    const char* gB = (const char*)g_b2 + (size_t)n0 * FC_ROWB;

    // ldmatrix lane row/col components (constant across chunks/ksteps)
    const int arow = (lane & 7) + 8*((lane >> 3) & 1);     // within 16-row frag
    const int acol = ((lane >> 4) & 1) * 16;               // k-halves 0/16 B
    const int brow = (lane & 7) + 8*(lane >> 4);           // within 16-n frag
    const int bcol = ((lane >> 3) & 1) * 16;

    float acc[4][4][4];
    #pragma unroll
    for (int i = 0; i < 4; i++)
        #pragma unroll
        for (int j = 0; j < 4; j++)
            #pragma unroll
            for (int r = 0; r < 4; r++) acc[i][j][r] = 0.f;

    #pragma unroll 1
    for (int c = 0; c < FC_CHUNKS; c++) {
        // stage A and B chunk tiles (each 128 rows x 128 B)
        #pragma unroll
        for (int i = 0; i < 4; i++) {
            int qi = tid + 256*i;
            int r = qi >> 3, qc = qi & 7;
            uint4 va = *(const uint4*)(gA + (size_t)r * FC_ROWB + c*128 + qc*16);
            *(uint4*)(smA + SWZ(r*128 + qc*16)) = va;
            uint4 vb = *(const uint4*)(gB + (size_t)r * FC_ROWB + c*128 + qc*16);
            *(uint4*)(smB + SWZ(r*128 + qc*16)) = vb;
        }
        __syncthreads();

        #pragma unroll
        for (int ks = 0; ks < 4; ks++) {
            uint32_t af[4][4];
            #pragma unroll
            for (int mi = 0; mi < 4; mi++) {
                int o = (wm*64 + mi*16 + arow)*128 + ks*32 + acol;
                LDSM_X4(af[mi], sa + SWZ(o));
            }
            uint32_t bf[2][4];
            #pragma unroll
            for (int np = 0; np < 2; np++) {
                int o = (wn*32 + np*16 + brow)*128 + ks*32 + bcol;
                LDSM_X4(bf[np], sb + SWZ(o));
            }
            #pragma unroll
            for (int mi = 0; mi < 4; mi++)
                #pragma unroll
                for (int nj = 0; nj < 4; nj++) {
                    uint32_t b0v = bf[nj >> 1][(nj & 1)*2 + 0];
                    uint32_t b1v = bf[nj >> 1][(nj & 1)*2 + 1];
                    MMA16816(acc[mi][nj], af[mi], b0v, b1v);
                }
        }
        __syncthreads();
    }

    // epilogue: bias + [B,T] row remap
    const int qrow = lane >> 2;
    const int qcol = (lane & 3) * 2;
    #pragma unroll
    for (int mi = 0; mi < 4; mi++) {
        int m  = m0 + wm*64 + mi*16 + qrow;
        int r0 = (m & 15) * T_ + (m >> 4);
        int m2 = m + 8;
        int r1 = (m2 & 15) * T_ + (m2 >> 4);
        #pragma unroll
        for (int nj = 0; nj < 4; nj++) {
            int col = n0 + wn*32 + nj*8 + qcol;
            float2 bv = *(const float2*)&fcb[col];
            float2 o0 = make_float2(acc[mi][nj][0] + bv.x, acc[mi][nj][1] + bv.y);
            float2 o1 = make_float2(acc[mi][nj][2] + bv.x, acc[mi][nj][3] + bv.y);
            *(float2*)&out[(size_t)r0 * V_ + col] = o0;
            *(float2*)&out[(size_t)r1 * V_ + col] = o1;
        }
    }
}

// ============================================================================
extern "C" void kernel_launch(void* const* d_in, const int* in_sizes, int n_in,
                              void* d_out, int out_size)
{
    const int*   x    = (const int*)  d_in[0];
    const float* emb  = (const float*)d_in[1];
    const float* Wih0 = (const float*)d_in[2];
    const float* Whh0 = (const float*)d_in[3];
    const float* bih0 = (const float*)d_in[4];
    const float* bhh0 = (const float*)d_in[5];
    const float* Wih1 = (const float*)d_in[6];
    const float* Whh1 = (const float*)d_in[7];
    const float* bih1 = (const float*)d_in[8];
    const float* bhh1 = (const float*)d_in[9];
    const float* fcW  = (const float*)d_in[10];
    const float* fcb  = (const float*)d_in[11];
    float* out = (float*)d_out;
    (void)in_sizes; (void)n_in; (void)out_size;

    float *xp, *ys;
    cudaGetSymbolAddress((void**)&xp, g_xproj);
    cudaGetSymbolAddress((void**)&ys, g_ys);

    cudaFuncSetAttribute(lstm_layer_persist,
                         cudaFuncAttributeMaxDynamicSharedMemorySize, SMEM_TOTAL_P);

    // B' conversion (depends only on fcW)
    conv_b_kernel<<<(V_*H_)/256, 256>>>(fcW);

    // ---- layer 0 ----
    sgemm_nt<1,0><<<dim3(G4/128, (B_*T_)/128), 256>>>(
        B_*T_, G4, E_, emb, E_, x, Wih0, E_, bih0, bhh0, xp, G4);
    zero_bar_kernel<<<1, 1>>>();
    lstm_layer_persist<<<128, 256, SMEM_TOTAL_P>>>(Whh0, xp, ys, out, 0);

    // ---- layer 1 ----
    sgemm_nt<0,0><<<dim3(G4/128, (B_*T_)/128), 256>>>(
        B_*T_, G4, H_, ys, H_, nullptr, Wih1, H_, bih1, bhh1, xp, G4);
    zero_bar_kernel<<<1, 1>>>();
    lstm_layer_persist<<<128, 256, SMEM_TOTAL_P>>>(Whh1, xp, ys, out, 1);

    // ---- FC on HMMA tensor pipe: A' conversion, then split-bf16 GEMM ----
    conv_a_kernel<<<(B_*T_*H_)/256, 256>>>();
    fc_mma_kernel<<<dim3((B_*T_)/128, V_/128), 256>>>(fcb, out);
}